// round 9
// baseline (speedup 1.0000x reference)
#include <cuda_runtime.h>
#include <cuda_fp16.h>
#include <math.h>

// ---------------------------------------------------------------------------
// out[e] = sigmoid( relu(x_e @ W1 + b1) @ W2 + b2 ),
// x_e = [h[src], rel_table[type], rel_table[q], time_table[time]]
//
// Decomposed into per-node / per-rel / per-time 128x128 projections (fp16),
// computed with HMMA tensor cores. Query projection + b1 folded into rel
// rows. Edge pass: 8 lanes/edge, 2 edges per group-iter, 12 LDG.128 in
// flight, W2 staged through smem to keep regs low / occupancy high.
// ---------------------------------------------------------------------------

#define D 128
#define MAX_NODES 100000
#define MAX_RELS  500
#define MAX_TIMES 1000

__device__ __align__(128) __half g_node_proj[(size_t)MAX_NODES * D];
__device__ __align__(128) __half g_rel_proj[(size_t)MAX_RELS * D];   // + rq@W1c + b1
__device__ __align__(128) __half g_time_proj[(size_t)MAX_TIMES * D];
__device__ __align__(16)  __half g_w2h[D];

// ---- mma / ldmatrix helpers ------------------------------------------------
__device__ __forceinline__ unsigned smem_u32(const void* p) {
    return (unsigned)__cvta_generic_to_shared(p);
}
__device__ __forceinline__ void ldm_x4(unsigned* r, unsigned addr) {
    asm volatile("ldmatrix.sync.aligned.m8n8.x4.shared.b16 {%0,%1,%2,%3}, [%4];"
                 : "=r"(r[0]), "=r"(r[1]), "=r"(r[2]), "=r"(r[3]) : "r"(addr));
}
__device__ __forceinline__ void ldm_x4_trans(unsigned* r, unsigned addr) {
    asm volatile("ldmatrix.sync.aligned.m8n8.x4.trans.shared.b16 {%0,%1,%2,%3}, [%4];"
                 : "=r"(r[0]), "=r"(r[1]), "=r"(r[2]), "=r"(r[3]) : "r"(addr));
}
__device__ __forceinline__ void mma_16816(float* c, const unsigned* a,
                                          const unsigned* b) {
    asm volatile(
        "mma.sync.aligned.m16n8k16.row.col.f32.f16.f16.f32 "
        "{%0,%1,%2,%3}, {%4,%5,%6,%7}, {%8,%9}, {%0,%1,%2,%3};"
        : "+f"(c[0]), "+f"(c[1]), "+f"(c[2]), "+f"(c[3])
        : "r"(a[0]), "r"(a[1]), "r"(a[2]), "r"(a[3]), "r"(b[0]), "r"(b[1]));
}

#define BM 128
#define KC 64

// ---------------------------------------------------------------------------
// Fused prep kernel: 128x128 output tile per block, K=128 in two KC=64 steps.
// 8 warps; warp w owns rows (w&3)*32..+32, cols (w>>2)*64..+64.
// ---------------------------------------------------------------------------
__global__ __launch_bounds__(256) void prep_kernel(
    const float* __restrict__ h,
    const float* __restrict__ rel_table,
    const float* __restrict__ time_table,
    const float* __restrict__ W1,
    const float* __restrict__ b1,
    const float* __restrict__ W2,
    const int* __restrict__ qptr,
    int n_nodes, int n_rels, int n_times)
{
    __shared__ __align__(16) __half As[128][72];    // M x KC (+pad)
    __shared__ __align__(16) __half Bs[64][136];    // KC x N (+pad)
    __shared__ float cbias_s[D];
    __shared__ float rq_s[D];

    const int tid  = threadIdx.x;
    const int lane = tid & 31;
    const int w    = tid >> 5;
    const int warp_m = (w & 3) * 32;
    const int warp_n = (w >> 2) * 64;

    const int nb_node = (n_nodes + BM - 1) / BM;
    const int nb_rel  = (n_rels  + BM - 1) / BM;

    if (blockIdx.x == 0 && tid < D)
        g_w2h[tid] = __float2half(__ldg(W2 + tid));
    if (tid < D) cbias_s[tid] = 0.f;

    const float* A;
    __half* C;
    int w_off, M, m0;
    bool is_rel = false;

    int bx = blockIdx.x;
    if (bx < nb_node) {
        A = h; C = g_node_proj; w_off = 0; M = n_nodes; m0 = bx * BM;
    } else if (bx < nb_node + nb_rel) {
        A = rel_table; C = g_rel_proj; w_off = 128; M = n_rels;
        m0 = (bx - nb_node) * BM; is_rel = true;
    } else {
        A = time_table; C = g_time_proj; w_off = 384; M = n_times;
        m0 = (bx - nb_node - nb_rel) * BM;
    }

    if (is_rel && tid < D) {
        int q = qptr[0];
        rq_s[tid] = __ldg(rel_table + (size_t)q * D + tid);
    }

    float acc[2][8][4];
#pragma unroll
    for (int mi = 0; mi < 2; mi++)
#pragma unroll
        for (int ni = 0; ni < 8; ni++)
#pragma unroll
            for (int c = 0; c < 4; c++) acc[mi][ni][c] = 0.f;

    for (int k0 = 0; k0 < D; k0 += KC) {
        __syncthreads();
        // A tile: 128 x 64, fp32 -> fp16.
#pragma unroll
        for (int it = 0; it < 8; it++) {
            int i   = tid + it * 256;
            int row = i >> 4;
            int c4  = i & 15;
            float4 v = make_float4(0.f, 0.f, 0.f, 0.f);
            int grow = m0 + row;
            if (grow < M)
                v = *(const float4*)(A + (size_t)grow * D + k0 + c4 * 4);
            __half2 h01 = __floats2half2_rn(v.x, v.y);
            __half2 h23 = __floats2half2_rn(v.z, v.w);
            uint2 pv;
            pv.x = *(unsigned*)&h01; pv.y = *(unsigned*)&h23;
            *(uint2*)(&As[row][c4 * 4]) = pv;
        }
        // B tile: 64 x 128, fp32 -> fp16.
#pragma unroll
        for (int it = 0; it < 8; it++) {
            int i   = tid + it * 256;
            int kk  = i >> 5;
            int c4  = i & 31;
            float4 v = *(const float4*)(W1 + (size_t)(w_off + k0 + kk) * D + c4 * 4);
            __half2 h01 = __floats2half2_rn(v.x, v.y);
            __half2 h23 = __floats2half2_rn(v.z, v.w);
            uint2 pv;
            pv.x = *(unsigned*)&h01; pv.y = *(unsigned*)&h23;
            *(uint2*)(&Bs[kk][c4 * 4]) = pv;
        }
        __syncthreads();

#pragma unroll
        for (int ks = 0; ks < KC / 16; ks++) {
            unsigned a[2][4];
            {
                int arow = (lane & 7) + ((lane >> 3) & 1) * 8;
                int acol = ks * 16 + (lane >> 4) * 8;
#pragma unroll
                for (int mi = 0; mi < 2; mi++)
                    ldm_x4(a[mi], smem_u32(&As[warp_m + mi * 16 + arow][acol]));
            }
            unsigned b[8][2];
            {
                int krow = ks * 16 + (lane & 7) + ((lane >> 3) & 1) * 8;
#pragma unroll
                for (int p = 0; p < 4; p++) {
                    unsigned r[4];
                    int ncol = warp_n + p * 16 + (lane >> 4) * 8;
                    ldm_x4_trans(r, smem_u32(&Bs[krow][ncol]));
                    b[2 * p][0]     = r[0]; b[2 * p][1]     = r[1];
                    b[2 * p + 1][0] = r[2]; b[2 * p + 1][1] = r[3];
                }
            }
#pragma unroll
            for (int mi = 0; mi < 2; mi++)
#pragma unroll
                for (int ni = 0; ni < 8; ni++)
                    mma_16816(acc[mi][ni], a[mi], b[ni]);
        }
    }

    if (is_rel) {
        if (tid < D) {
            int j = tid;
            float s = __ldg(b1 + j);
            const float* Wc = W1 + (size_t)256 * D + j;
#pragma unroll 8
            for (int k = 0; k < D; k++)
                s += rq_s[k] * __ldg(Wc + (size_t)k * D);
            cbias_s[j] = s;
        }
        __syncthreads();
    }

    const int erow = lane >> 2;
    const int ecol = (lane & 3) * 2;
#pragma unroll
    for (int mi = 0; mi < 2; mi++) {
#pragma unroll
        for (int ni = 0; ni < 8; ni++) {
            int col = warp_n + ni * 8 + ecol;
            float cb0 = cbias_s[col], cb1 = cbias_s[col + 1];
            int r0 = m0 + warp_m + mi * 16 + erow;
            if (r0 < M) {
                __half2 v = __floats2half2_rn(acc[mi][ni][0] + cb0,
                                              acc[mi][ni][1] + cb1);
                *(__half2*)(C + (size_t)r0 * D + col) = v;
            }
            int r1 = r0 + 8;
            if (r1 < M) {
                __half2 v = __floats2half2_rn(acc[mi][ni][2] + cb0,
                                              acc[mi][ni][3] + cb1);
                *(__half2*)(C + (size_t)r1 * D + col) = v;
            }
        }
    }
}

// ---------------------------------------------------------------------------
// Edge pass: 8 lanes per edge, lane l covers features [16l, 16l+16)
// (two uint4 per table). 2 edges (one int2 index pair) per group-iteration.
// W2 staged through smem; occupancy pinned at 5 blocks/SM.
// ---------------------------------------------------------------------------
__device__ __forceinline__ float edge_partial(uint4 av, uint4 bv, uint4 cv,
                                              uint4 wv)
{
    const __half2 z2 = __float2half2_rn(0.f);
    __half2 acc;
    {
        __half2 x = __hmax2(__hadd2(__hadd2(*(__half2*)&av.x, *(__half2*)&bv.x),
                                    *(__half2*)&cv.x), z2);
        acc = __hmul2(x, *(__half2*)&wv.x);
    }
    {
        __half2 x = __hmax2(__hadd2(__hadd2(*(__half2*)&av.y, *(__half2*)&bv.y),
                                    *(__half2*)&cv.y), z2);
        acc = __hfma2(x, *(__half2*)&wv.y, acc);
    }
    {
        __half2 x = __hmax2(__hadd2(__hadd2(*(__half2*)&av.z, *(__half2*)&bv.z),
                                    *(__half2*)&cv.z), z2);
        acc = __hfma2(x, *(__half2*)&wv.z, acc);
    }
    {
        __half2 x = __hmax2(__hadd2(__hadd2(*(__half2*)&av.w, *(__half2*)&bv.w),
                                    *(__half2*)&cv.w), z2);
        acc = __hfma2(x, *(__half2*)&wv.w, acc);
    }
    float2 f = __half22float2(acc);
    return f.x + f.y;
}

__global__ __launch_bounds__(256, 5) void edge_kernel(
    const int* __restrict__ edge_src,
    const int* __restrict__ edge_type,
    const int* __restrict__ edge_time,
    const float* __restrict__ b2,
    float* __restrict__ out, int E)
{
    __shared__ __align__(16) uint4 w2_s[16];

    const int l = threadIdx.x & 7;                          // lane in 8-group
    const int group  = (int)((blockIdx.x * 256u + threadIdx.x) >> 3);
    const int ngroup = (int)(gridDim.x * 256u / 8u);

    if (threadIdx.x < 16)
        w2_s[threadIdx.x] = ((const uint4*)g_w2h)[threadIdx.x];
    __syncthreads();

    const uint4* __restrict__ np = (const uint4*)g_node_proj;
    const uint4* __restrict__ rp = (const uint4*)g_rel_proj;
    const uint4* __restrict__ tp = (const uint4*)g_time_proj;

    const float b2v = __ldg(b2);

    const int npair = E >> 1;
    for (int p = group; p < npair; p += ngroup) {
        int2 s = __ldg((const int2*)edge_src  + p);
        int2 r = __ldg((const int2*)edge_type + p);
        int2 t = __ldg((const int2*)edge_time + p);

        size_t oA = (size_t)l * 2;
        uint4 avA0 = np[(size_t)s.x * 16 + oA], avA1 = np[(size_t)s.x * 16 + oA + 1];
        uint4 bvA0 = rp[(size_t)r.x * 16 + oA], bvA1 = rp[(size_t)r.x * 16 + oA + 1];
        uint4 cvA0 = tp[(size_t)t.x * 16 + oA], cvA1 = tp[(size_t)t.x * 16 + oA + 1];
        uint4 avB0 = np[(size_t)s.y * 16 + oA], avB1 = np[(size_t)s.y * 16 + oA + 1];
        uint4 bvB0 = rp[(size_t)r.y * 16 + oA], bvB1 = rp[(size_t)r.y * 16 + oA + 1];
        uint4 cvB0 = tp[(size_t)t.y * 16 + oA], cvB1 = tp[(size_t)t.y * 16 + oA + 1];

        uint4 wv0 = w2_s[l * 2];
        uint4 wv1 = w2_s[l * 2 + 1];

        float dA = edge_partial(avA0, bvA0, cvA0, wv0)
                 + edge_partial(avA1, bvA1, cvA1, wv1);
        float dB = edge_partial(avB0, bvB0, cvB0, wv0)
                 + edge_partial(avB1, bvB1, cvB1, wv1);

#pragma unroll
        for (int off = 4; off; off >>= 1) {
            dA += __shfl_xor_sync(0xffffffffu, dA, off);
            dB += __shfl_xor_sync(0xffffffffu, dB, off);
        }

        if (l == 0) {
            out[p * 2]     = 1.f / (1.f + __expf(-(dA + b2v)));
            out[p * 2 + 1] = 1.f / (1.f + __expf(-(dB + b2v)));
        }
    }

    // Odd tail edge handled by group 0.
    if ((E & 1) && group == 0) {
        int e = E - 1;
        int s = __ldg(edge_src + e);
        int r = __ldg(edge_type + e);
        int t = __ldg(edge_time + e);
        size_t oA = (size_t)l * 2;
        uint4 wv0 = w2_s[l * 2];
        uint4 wv1 = w2_s[l * 2 + 1];
        float d = edge_partial(np[(size_t)s * 16 + oA], rp[(size_t)r * 16 + oA],
                               tp[(size_t)t * 16 + oA], wv0)
                + edge_partial(np[(size_t)s * 16 + oA + 1], rp[(size_t)r * 16 + oA + 1],
                               tp[(size_t)t * 16 + oA + 1], wv1);
#pragma unroll
        for (int off = 4; off; off >>= 1)
            d += __shfl_xor_sync(0xffffffffu, d, off);
        if (l == 0)
            out[e] = 1.f / (1.f + __expf(-(d + b2v)));
    }
}

// ---------------------------------------------------------------------------
extern "C" void kernel_launch(void* const* d_in, const int* in_sizes, int n_in,
                              void* d_out, int out_size)
{
    const float* h          = (const float*)d_in[0];
    const int*   edge_index = (const int*)d_in[1];
    const int*   edge_type  = (const int*)d_in[2];
    const int*   edge_time  = (const int*)d_in[3];
    const int*   query_rel  = (const int*)d_in[4];
    const float* rel_table  = (const float*)d_in[5];
    const float* time_table = (const float*)d_in[6];
    const float* W1         = (const float*)d_in[7];
    const float* b1         = (const float*)d_in[8];
    const float* W2         = (const float*)d_in[9];
    const float* b2         = (const float*)d_in[10];
    float*       out        = (float*)d_out;

    const int n_nodes = in_sizes[0] / D;
    const int n_rels  = in_sizes[5] / D;
    const int n_times = in_sizes[6] / D;
    const int E       = in_sizes[2];

    const int nb_node = (n_nodes + BM - 1) / BM;
    const int nb_rel  = (n_rels  + BM - 1) / BM;
    const int nb_time = (n_times + BM - 1) / BM;

    prep_kernel<<<nb_node + nb_rel + nb_time, 256>>>(
        h, rel_table, time_table, W1, b1, W2, query_rel,
        n_nodes, n_rels, n_times);

    edge_kernel<<<2048, 256>>>(edge_index, edge_type, edge_time, b2, out, E);
}

// round 10
// speedup vs baseline: 1.0257x; 1.0257x over previous
#include <cuda_runtime.h>
#include <cuda_fp16.h>
#include <math.h>

// ---------------------------------------------------------------------------
// out[e] = sigmoid( relu(x_e @ W1 + b1) @ W2 + b2 ),
// x_e = [h[src], rel_table[type], rel_table[q], time_table[time]]
//
// Decomposed into per-node / per-rel / per-time 128x128 projections (fp16),
// computed with HMMA tensor cores. Query projection + b1 folded into rel
// rows. Edge pass: 8 lanes/edge, block-strided addressing (each LDG.128
// covers exactly one 128B line -> 6 L1 wavefronts/edge, the minimum).
// ---------------------------------------------------------------------------

#define D 128
#define MAX_NODES 100000
#define MAX_RELS  500
#define MAX_TIMES 1000

__device__ __align__(128) __half g_node_proj[(size_t)MAX_NODES * D];
__device__ __align__(128) __half g_rel_proj[(size_t)MAX_RELS * D];   // + rq@W1c + b1
__device__ __align__(128) __half g_time_proj[(size_t)MAX_TIMES * D];
__device__ __align__(16)  __half g_w2h[D];

// ---- mma / ldmatrix helpers ------------------------------------------------
__device__ __forceinline__ unsigned smem_u32(const void* p) {
    return (unsigned)__cvta_generic_to_shared(p);
}
__device__ __forceinline__ void ldm_x4(unsigned* r, unsigned addr) {
    asm volatile("ldmatrix.sync.aligned.m8n8.x4.shared.b16 {%0,%1,%2,%3}, [%4];"
                 : "=r"(r[0]), "=r"(r[1]), "=r"(r[2]), "=r"(r[3]) : "r"(addr));
}
__device__ __forceinline__ void ldm_x4_trans(unsigned* r, unsigned addr) {
    asm volatile("ldmatrix.sync.aligned.m8n8.x4.trans.shared.b16 {%0,%1,%2,%3}, [%4];"
                 : "=r"(r[0]), "=r"(r[1]), "=r"(r[2]), "=r"(r[3]) : "r"(addr));
}
__device__ __forceinline__ void mma_16816(float* c, const unsigned* a,
                                          const unsigned* b) {
    asm volatile(
        "mma.sync.aligned.m16n8k16.row.col.f32.f16.f16.f32 "
        "{%0,%1,%2,%3}, {%4,%5,%6,%7}, {%8,%9}, {%0,%1,%2,%3};"
        : "+f"(c[0]), "+f"(c[1]), "+f"(c[2]), "+f"(c[3])
        : "r"(a[0]), "r"(a[1]), "r"(a[2]), "r"(a[3]), "r"(b[0]), "r"(b[1]));
}

#define BM 128
#define KC 64

// ---------------------------------------------------------------------------
// Fused prep kernel: 128x128 output tile per block, K=128 in two KC=64 steps.
// 8 warps; warp w owns rows (w&3)*32..+32, cols (w>>2)*64..+64.
// ---------------------------------------------------------------------------
__global__ __launch_bounds__(256) void prep_kernel(
    const float* __restrict__ h,
    const float* __restrict__ rel_table,
    const float* __restrict__ time_table,
    const float* __restrict__ W1,
    const float* __restrict__ b1,
    const float* __restrict__ W2,
    const int* __restrict__ qptr,
    int n_nodes, int n_rels, int n_times)
{
    __shared__ __align__(16) __half As[128][72];    // M x KC (+pad)
    __shared__ __align__(16) __half Bs[64][136];    // KC x N (+pad)
    __shared__ float cbias_s[D];
    __shared__ float rq_s[D];

    const int tid  = threadIdx.x;
    const int lane = tid & 31;
    const int w    = tid >> 5;
    const int warp_m = (w & 3) * 32;
    const int warp_n = (w >> 2) * 64;

    const int nb_node = (n_nodes + BM - 1) / BM;
    const int nb_rel  = (n_rels  + BM - 1) / BM;

    if (blockIdx.x == 0 && tid < D)
        g_w2h[tid] = __float2half(__ldg(W2 + tid));
    if (tid < D) cbias_s[tid] = 0.f;

    const float* A;
    __half* C;
    int w_off, M, m0;
    bool is_rel = false;

    int bx = blockIdx.x;
    if (bx < nb_node) {
        A = h; C = g_node_proj; w_off = 0; M = n_nodes; m0 = bx * BM;
    } else if (bx < nb_node + nb_rel) {
        A = rel_table; C = g_rel_proj; w_off = 128; M = n_rels;
        m0 = (bx - nb_node) * BM; is_rel = true;
    } else {
        A = time_table; C = g_time_proj; w_off = 384; M = n_times;
        m0 = (bx - nb_node - nb_rel) * BM;
    }

    if (is_rel && tid < D) {
        int q = qptr[0];
        rq_s[tid] = __ldg(rel_table + (size_t)q * D + tid);
    }

    float acc[2][8][4];
#pragma unroll
    for (int mi = 0; mi < 2; mi++)
#pragma unroll
        for (int ni = 0; ni < 8; ni++)
#pragma unroll
            for (int c = 0; c < 4; c++) acc[mi][ni][c] = 0.f;

    for (int k0 = 0; k0 < D; k0 += KC) {
        __syncthreads();
        // A tile: 128 x 64, fp32 -> fp16.
#pragma unroll
        for (int it = 0; it < 8; it++) {
            int i   = tid + it * 256;
            int row = i >> 4;
            int c4  = i & 15;
            float4 v = make_float4(0.f, 0.f, 0.f, 0.f);
            int grow = m0 + row;
            if (grow < M)
                v = *(const float4*)(A + (size_t)grow * D + k0 + c4 * 4);
            __half2 h01 = __floats2half2_rn(v.x, v.y);
            __half2 h23 = __floats2half2_rn(v.z, v.w);
            uint2 pv;
            pv.x = *(unsigned*)&h01; pv.y = *(unsigned*)&h23;
            *(uint2*)(&As[row][c4 * 4]) = pv;
        }
        // B tile: 64 x 128, fp32 -> fp16.
#pragma unroll
        for (int it = 0; it < 8; it++) {
            int i   = tid + it * 256;
            int kk  = i >> 5;
            int c4  = i & 31;
            float4 v = *(const float4*)(W1 + (size_t)(w_off + k0 + kk) * D + c4 * 4);
            __half2 h01 = __floats2half2_rn(v.x, v.y);
            __half2 h23 = __floats2half2_rn(v.z, v.w);
            uint2 pv;
            pv.x = *(unsigned*)&h01; pv.y = *(unsigned*)&h23;
            *(uint2*)(&Bs[kk][c4 * 4]) = pv;
        }
        __syncthreads();

#pragma unroll
        for (int ks = 0; ks < KC / 16; ks++) {
            unsigned a[2][4];
            {
                int arow = (lane & 7) + ((lane >> 3) & 1) * 8;
                int acol = ks * 16 + (lane >> 4) * 8;
#pragma unroll
                for (int mi = 0; mi < 2; mi++)
                    ldm_x4(a[mi], smem_u32(&As[warp_m + mi * 16 + arow][acol]));
            }
            unsigned b[8][2];
            {
                int krow = ks * 16 + (lane & 7) + ((lane >> 3) & 1) * 8;
#pragma unroll
                for (int p = 0; p < 4; p++) {
                    unsigned r[4];
                    int ncol = warp_n + p * 16 + (lane >> 4) * 8;
                    ldm_x4_trans(r, smem_u32(&Bs[krow][ncol]));
                    b[2 * p][0]     = r[0]; b[2 * p][1]     = r[1];
                    b[2 * p + 1][0] = r[2]; b[2 * p + 1][1] = r[3];
                }
            }
#pragma unroll
            for (int mi = 0; mi < 2; mi++)
#pragma unroll
                for (int ni = 0; ni < 8; ni++)
                    mma_16816(acc[mi][ni], a[mi], b[ni]);
        }
    }

    if (is_rel) {
        if (tid < D) {
            int j = tid;
            float s = __ldg(b1 + j);
            const float* Wc = W1 + (size_t)256 * D + j;
#pragma unroll 8
            for (int k = 0; k < D; k++)
                s += rq_s[k] * __ldg(Wc + (size_t)k * D);
            cbias_s[j] = s;
        }
        __syncthreads();
    }

    const int erow = lane >> 2;
    const int ecol = (lane & 3) * 2;
#pragma unroll
    for (int mi = 0; mi < 2; mi++) {
#pragma unroll
        for (int ni = 0; ni < 8; ni++) {
            int col = warp_n + ni * 8 + ecol;
            float cb0 = cbias_s[col], cb1 = cbias_s[col + 1];
            int r0 = m0 + warp_m + mi * 16 + erow;
            if (r0 < M) {
                __half2 v = __floats2half2_rn(acc[mi][ni][0] + cb0,
                                              acc[mi][ni][1] + cb1);
                *(__half2*)(C + (size_t)r0 * D + col) = v;
            }
            int r1 = r0 + 8;
            if (r1 < M) {
                __half2 v = __floats2half2_rn(acc[mi][ni][2] + cb0,
                                              acc[mi][ni][3] + cb1);
                *(__half2*)(C + (size_t)r1 * D + col) = v;
            }
        }
    }
}

// ---------------------------------------------------------------------------
// Edge pass: 8 lanes per edge. Lane l covers uint4 slots {l, l+8}:
// load 0 -> bytes [16l, 16l+16)      (first 128B line of the row)
// load 1 -> bytes [128+16l, ...)     (second 128B line)
// Each LDG.128 thus maps to exactly ONE 128B line -> minimal wavefronts.
// 2 edges (one int2 index pair) per group-iteration.
// ---------------------------------------------------------------------------
__device__ __forceinline__ float edge_partial(uint4 av, uint4 bv, uint4 cv,
                                              uint4 wv)
{
    const __half2 z2 = __float2half2_rn(0.f);
    __half2 acc;
    {
        __half2 x = __hmax2(__hadd2(__hadd2(*(__half2*)&av.x, *(__half2*)&bv.x),
                                    *(__half2*)&cv.x), z2);
        acc = __hmul2(x, *(__half2*)&wv.x);
    }
    {
        __half2 x = __hmax2(__hadd2(__hadd2(*(__half2*)&av.y, *(__half2*)&bv.y),
                                    *(__half2*)&cv.y), z2);
        acc = __hfma2(x, *(__half2*)&wv.y, acc);
    }
    {
        __half2 x = __hmax2(__hadd2(__hadd2(*(__half2*)&av.z, *(__half2*)&bv.z),
                                    *(__half2*)&cv.z), z2);
        acc = __hfma2(x, *(__half2*)&wv.z, acc);
    }
    {
        __half2 x = __hmax2(__hadd2(__hadd2(*(__half2*)&av.w, *(__half2*)&bv.w),
                                    *(__half2*)&cv.w), z2);
        acc = __hfma2(x, *(__half2*)&wv.w, acc);
    }
    float2 f = __half22float2(acc);
    return f.x + f.y;
}

__global__ __launch_bounds__(256, 5) void edge_kernel(
    const int* __restrict__ edge_src,
    const int* __restrict__ edge_type,
    const int* __restrict__ edge_time,
    const float* __restrict__ b2,
    float* __restrict__ out, int E)
{
    __shared__ __align__(16) uint4 w2_s[16];

    const int l = threadIdx.x & 7;                          // lane in 8-group
    const int group  = (int)((blockIdx.x * 256u + threadIdx.x) >> 3);
    const int ngroup = (int)(gridDim.x * 256u / 8u);

    if (threadIdx.x < 16)
        w2_s[threadIdx.x] = ((const uint4*)g_w2h)[threadIdx.x];
    __syncthreads();

    const uint4* __restrict__ np = (const uint4*)g_node_proj;
    const uint4* __restrict__ rp = (const uint4*)g_rel_proj;
    const uint4* __restrict__ tp = (const uint4*)g_time_proj;

    const float b2v = __ldg(b2);

    const int npair = E >> 1;
    for (int p = group; p < npair; p += ngroup) {
        int2 s = __ldg((const int2*)edge_src  + p);
        int2 r = __ldg((const int2*)edge_type + p);
        int2 t = __ldg((const int2*)edge_time + p);

        // Block-strided slots: l (line 0) and l+8 (line 1).
        size_t o0 = (size_t)l;
        size_t o1 = (size_t)l + 8;
        uint4 avA0 = np[(size_t)s.x * 16 + o0], avA1 = np[(size_t)s.x * 16 + o1];
        uint4 bvA0 = rp[(size_t)r.x * 16 + o0], bvA1 = rp[(size_t)r.x * 16 + o1];
        uint4 cvA0 = tp[(size_t)t.x * 16 + o0], cvA1 = tp[(size_t)t.x * 16 + o1];
        uint4 avB0 = np[(size_t)s.y * 16 + o0], avB1 = np[(size_t)s.y * 16 + o1];
        uint4 bvB0 = rp[(size_t)r.y * 16 + o0], bvB1 = rp[(size_t)r.y * 16 + o1];
        uint4 cvB0 = tp[(size_t)t.y * 16 + o0], cvB1 = tp[(size_t)t.y * 16 + o1];

        uint4 wv0 = w2_s[l];
        uint4 wv1 = w2_s[l + 8];

        float dA = edge_partial(avA0, bvA0, cvA0, wv0)
                 + edge_partial(avA1, bvA1, cvA1, wv1);
        float dB = edge_partial(avB0, bvB0, cvB0, wv0)
                 + edge_partial(avB1, bvB1, cvB1, wv1);

#pragma unroll
        for (int off = 4; off; off >>= 1) {
            dA += __shfl_xor_sync(0xffffffffu, dA, off);
            dB += __shfl_xor_sync(0xffffffffu, dB, off);
        }

        if (l == 0) {
            out[p * 2]     = 1.f / (1.f + __expf(-(dA + b2v)));
            out[p * 2 + 1] = 1.f / (1.f + __expf(-(dB + b2v)));
        }
    }

    // Odd tail edge handled by group 0.
    if ((E & 1) && group == 0) {
        int e = E - 1;
        int s = __ldg(edge_src + e);
        int r = __ldg(edge_type + e);
        int t = __ldg(edge_time + e);
        size_t o0 = (size_t)l;
        size_t o1 = (size_t)l + 8;
        uint4 wv0 = w2_s[l];
        uint4 wv1 = w2_s[l + 8];
        float d = edge_partial(np[(size_t)s * 16 + o0], rp[(size_t)r * 16 + o0],
                               tp[(size_t)t * 16 + o0], wv0)
                + edge_partial(np[(size_t)s * 16 + o1], rp[(size_t)r * 16 + o1],
                               tp[(size_t)t * 16 + o1], wv1);
#pragma unroll
        for (int off = 4; off; off >>= 1)
            d += __shfl_xor_sync(0xffffffffu, d, off);
        if (l == 0)
            out[e] = 1.f / (1.f + __expf(-(d + b2v)));
    }
}

// ---------------------------------------------------------------------------
extern "C" void kernel_launch(void* const* d_in, const int* in_sizes, int n_in,
                              void* d_out, int out_size)
{
    const float* h          = (const float*)d_in[0];
    const int*   edge_index = (const int*)d_in[1];
    const int*   edge_type  = (const int*)d_in[2];
    const int*   edge_time  = (const int*)d_in[3];
    const int*   query_rel  = (const int*)d_in[4];
    const float* rel_table  = (const float*)d_in[5];
    const float* time_table = (const float*)d_in[6];
    const float* W1         = (const float*)d_in[7];
    const float* b1         = (const float*)d_in[8];
    const float* W2         = (const float*)d_in[9];
    const float* b2         = (const float*)d_in[10];
    float*       out        = (float*)d_out;

    const int n_nodes = in_sizes[0] / D;
    const int n_rels  = in_sizes[5] / D;
    const int n_times = in_sizes[6] / D;
    const int E       = in_sizes[2];

    const int nb_node = (n_nodes + BM - 1) / BM;
    const int nb_rel  = (n_rels  + BM - 1) / BM;
    const int nb_time = (n_times + BM - 1) / BM;

    prep_kernel<<<nb_node + nb_rel + nb_time, 256>>>(
        h, rel_table, time_table, W1, b1, W2, query_rel,
        n_nodes, n_rels, n_times);

    edge_kernel<<<2048, 256>>>(edge_index, edge_type, edge_time, b2, out, E);
}

// round 11
// speedup vs baseline: 1.0713x; 1.0445x over previous
#include <cuda_runtime.h>
#include <cuda_fp16.h>
#include <math.h>

// ---------------------------------------------------------------------------
// out[e] = sigmoid( relu(x_e @ W1 + b1) @ W2 + b2 ),
// x_e = [h[src], rel_table[type], rel_table[q], time_table[time]]
//
// Decomposed into per-node / per-rel / per-time 128x128 projections (fp16),
// computed with HMMA tensor cores. Query projection + b1 folded into rel
// rows. Edge pass: 8 lanes/edge, 2 edges per group-iter, index loads
// software-pipelined one iteration ahead to hide streamed-index latency.
// ---------------------------------------------------------------------------

#define D 128
#define MAX_NODES 100000
#define MAX_RELS  500
#define MAX_TIMES 1000

__device__ __align__(128) __half g_node_proj[(size_t)MAX_NODES * D];
__device__ __align__(128) __half g_rel_proj[(size_t)MAX_RELS * D];   // + rq@W1c + b1
__device__ __align__(128) __half g_time_proj[(size_t)MAX_TIMES * D];
__device__ __align__(16)  __half g_w2h[D];

// ---- mma / ldmatrix helpers ------------------------------------------------
__device__ __forceinline__ unsigned smem_u32(const void* p) {
    return (unsigned)__cvta_generic_to_shared(p);
}
__device__ __forceinline__ void ldm_x4(unsigned* r, unsigned addr) {
    asm volatile("ldmatrix.sync.aligned.m8n8.x4.shared.b16 {%0,%1,%2,%3}, [%4];"
                 : "=r"(r[0]), "=r"(r[1]), "=r"(r[2]), "=r"(r[3]) : "r"(addr));
}
__device__ __forceinline__ void ldm_x4_trans(unsigned* r, unsigned addr) {
    asm volatile("ldmatrix.sync.aligned.m8n8.x4.trans.shared.b16 {%0,%1,%2,%3}, [%4];"
                 : "=r"(r[0]), "=r"(r[1]), "=r"(r[2]), "=r"(r[3]) : "r"(addr));
}
__device__ __forceinline__ void mma_16816(float* c, const unsigned* a,
                                          const unsigned* b) {
    asm volatile(
        "mma.sync.aligned.m16n8k16.row.col.f32.f16.f16.f32 "
        "{%0,%1,%2,%3}, {%4,%5,%6,%7}, {%8,%9}, {%0,%1,%2,%3};"
        : "+f"(c[0]), "+f"(c[1]), "+f"(c[2]), "+f"(c[3])
        : "r"(a[0]), "r"(a[1]), "r"(a[2]), "r"(a[3]), "r"(b[0]), "r"(b[1]));
}

#define BM 128
#define KC 64

// ---------------------------------------------------------------------------
// Fused prep kernel: 128x128 output tile per block, K=128 in two KC=64 steps.
// 8 warps; warp w owns rows (w&3)*32..+32, cols (w>>2)*64..+64.
// ---------------------------------------------------------------------------
__global__ __launch_bounds__(256) void prep_kernel(
    const float* __restrict__ h,
    const float* __restrict__ rel_table,
    const float* __restrict__ time_table,
    const float* __restrict__ W1,
    const float* __restrict__ b1,
    const float* __restrict__ W2,
    const int* __restrict__ qptr,
    int n_nodes, int n_rels, int n_times)
{
    __shared__ __align__(16) __half As[128][72];    // M x KC (+pad)
    __shared__ __align__(16) __half Bs[64][136];    // KC x N (+pad)
    __shared__ float cbias_s[D];
    __shared__ float rq_s[D];

    const int tid  = threadIdx.x;
    const int lane = tid & 31;
    const int w    = tid >> 5;
    const int warp_m = (w & 3) * 32;
    const int warp_n = (w >> 2) * 64;

    const int nb_node = (n_nodes + BM - 1) / BM;
    const int nb_rel  = (n_rels  + BM - 1) / BM;

    if (blockIdx.x == 0 && tid < D)
        g_w2h[tid] = __float2half(__ldg(W2 + tid));
    if (tid < D) cbias_s[tid] = 0.f;

    const float* A;
    __half* C;
    int w_off, M, m0;
    bool is_rel = false;

    int bx = blockIdx.x;
    if (bx < nb_node) {
        A = h; C = g_node_proj; w_off = 0; M = n_nodes; m0 = bx * BM;
    } else if (bx < nb_node + nb_rel) {
        A = rel_table; C = g_rel_proj; w_off = 128; M = n_rels;
        m0 = (bx - nb_node) * BM; is_rel = true;
    } else {
        A = time_table; C = g_time_proj; w_off = 384; M = n_times;
        m0 = (bx - nb_node - nb_rel) * BM;
    }

    if (is_rel && tid < D) {
        int q = qptr[0];
        rq_s[tid] = __ldg(rel_table + (size_t)q * D + tid);
    }

    float acc[2][8][4];
#pragma unroll
    for (int mi = 0; mi < 2; mi++)
#pragma unroll
        for (int ni = 0; ni < 8; ni++)
#pragma unroll
            for (int c = 0; c < 4; c++) acc[mi][ni][c] = 0.f;

    for (int k0 = 0; k0 < D; k0 += KC) {
        __syncthreads();
        // A tile: 128 x 64, fp32 -> fp16.
#pragma unroll
        for (int it = 0; it < 8; it++) {
            int i   = tid + it * 256;
            int row = i >> 4;
            int c4  = i & 15;
            float4 v = make_float4(0.f, 0.f, 0.f, 0.f);
            int grow = m0 + row;
            if (grow < M)
                v = *(const float4*)(A + (size_t)grow * D + k0 + c4 * 4);
            __half2 h01 = __floats2half2_rn(v.x, v.y);
            __half2 h23 = __floats2half2_rn(v.z, v.w);
            uint2 pv;
            pv.x = *(unsigned*)&h01; pv.y = *(unsigned*)&h23;
            *(uint2*)(&As[row][c4 * 4]) = pv;
        }
        // B tile: 64 x 128, fp32 -> fp16.
#pragma unroll
        for (int it = 0; it < 8; it++) {
            int i   = tid + it * 256;
            int kk  = i >> 5;
            int c4  = i & 31;
            float4 v = *(const float4*)(W1 + (size_t)(w_off + k0 + kk) * D + c4 * 4);
            __half2 h01 = __floats2half2_rn(v.x, v.y);
            __half2 h23 = __floats2half2_rn(v.z, v.w);
            uint2 pv;
            pv.x = *(unsigned*)&h01; pv.y = *(unsigned*)&h23;
            *(uint2*)(&Bs[kk][c4 * 4]) = pv;
        }
        __syncthreads();

#pragma unroll
        for (int ks = 0; ks < KC / 16; ks++) {
            unsigned a[2][4];
            {
                int arow = (lane & 7) + ((lane >> 3) & 1) * 8;
                int acol = ks * 16 + (lane >> 4) * 8;
#pragma unroll
                for (int mi = 0; mi < 2; mi++)
                    ldm_x4(a[mi], smem_u32(&As[warp_m + mi * 16 + arow][acol]));
            }
            unsigned b[8][2];
            {
                int krow = ks * 16 + (lane & 7) + ((lane >> 3) & 1) * 8;
#pragma unroll
                for (int p = 0; p < 4; p++) {
                    unsigned r[4];
                    int ncol = warp_n + p * 16 + (lane >> 4) * 8;
                    ldm_x4_trans(r, smem_u32(&Bs[krow][ncol]));
                    b[2 * p][0]     = r[0]; b[2 * p][1]     = r[1];
                    b[2 * p + 1][0] = r[2]; b[2 * p + 1][1] = r[3];
                }
            }
#pragma unroll
            for (int mi = 0; mi < 2; mi++)
#pragma unroll
                for (int ni = 0; ni < 8; ni++)
                    mma_16816(acc[mi][ni], a[mi], b[ni]);
        }
    }

    if (is_rel) {
        if (tid < D) {
            int j = tid;
            float s = __ldg(b1 + j);
            const float* Wc = W1 + (size_t)256 * D + j;
#pragma unroll 8
            for (int k = 0; k < D; k++)
                s += rq_s[k] * __ldg(Wc + (size_t)k * D);
            cbias_s[j] = s;
        }
        __syncthreads();
    }

    const int erow = lane >> 2;
    const int ecol = (lane & 3) * 2;
#pragma unroll
    for (int mi = 0; mi < 2; mi++) {
#pragma unroll
        for (int ni = 0; ni < 8; ni++) {
            int col = warp_n + ni * 8 + ecol;
            float cb0 = cbias_s[col], cb1 = cbias_s[col + 1];
            int r0 = m0 + warp_m + mi * 16 + erow;
            if (r0 < M) {
                __half2 v = __floats2half2_rn(acc[mi][ni][0] + cb0,
                                              acc[mi][ni][1] + cb1);
                *(__half2*)(C + (size_t)r0 * D + col) = v;
            }
            int r1 = r0 + 8;
            if (r1 < M) {
                __half2 v = __floats2half2_rn(acc[mi][ni][2] + cb0,
                                              acc[mi][ni][3] + cb1);
                *(__half2*)(C + (size_t)r1 * D + col) = v;
            }
        }
    }
}

// ---------------------------------------------------------------------------
// Edge pass: 8 lanes per edge, lane l covers uint4 slots {l, l+8}.
// Index loads for iteration p+ngroup are prefetched during iteration p,
// overlapping streamed-index latency with gathers/math.
// ---------------------------------------------------------------------------
__device__ __forceinline__ float edge_partial(uint4 av, uint4 bv, uint4 cv,
                                              uint4 wv)
{
    const __half2 z2 = __float2half2_rn(0.f);
    __half2 acc;
    {
        __half2 x = __hmax2(__hadd2(__hadd2(*(__half2*)&av.x, *(__half2*)&bv.x),
                                    *(__half2*)&cv.x), z2);
        acc = __hmul2(x, *(__half2*)&wv.x);
    }
    {
        __half2 x = __hmax2(__hadd2(__hadd2(*(__half2*)&av.y, *(__half2*)&bv.y),
                                    *(__half2*)&cv.y), z2);
        acc = __hfma2(x, *(__half2*)&wv.y, acc);
    }
    {
        __half2 x = __hmax2(__hadd2(__hadd2(*(__half2*)&av.z, *(__half2*)&bv.z),
                                    *(__half2*)&cv.z), z2);
        acc = __hfma2(x, *(__half2*)&wv.z, acc);
    }
    {
        __half2 x = __hmax2(__hadd2(__hadd2(*(__half2*)&av.w, *(__half2*)&bv.w),
                                    *(__half2*)&cv.w), z2);
        acc = __hfma2(x, *(__half2*)&wv.w, acc);
    }
    float2 f = __half22float2(acc);
    return f.x + f.y;
}

__global__ __launch_bounds__(256, 5) void edge_kernel(
    const int* __restrict__ edge_src,
    const int* __restrict__ edge_type,
    const int* __restrict__ edge_time,
    const float* __restrict__ b2,
    float* __restrict__ out, int E)
{
    __shared__ __align__(16) uint4 w2_s[16];

    const int l = threadIdx.x & 7;                          // lane in 8-group
    const int group  = (int)((blockIdx.x * 256u + threadIdx.x) >> 3);
    const int ngroup = (int)(gridDim.x * 256u / 8u);

    if (threadIdx.x < 16)
        w2_s[threadIdx.x] = ((const uint4*)g_w2h)[threadIdx.x];
    __syncthreads();

    const uint4* __restrict__ np = (const uint4*)g_node_proj;
    const uint4* __restrict__ rp = (const uint4*)g_rel_proj;
    const uint4* __restrict__ tp = (const uint4*)g_time_proj;

    const float b2v = __ldg(b2);
    const uint4 wv0 = w2_s[l];
    const uint4 wv1 = w2_s[l + 8];

    const int npair = E >> 1;

    // Prologue: prefetch first iteration's indices.
    int p = group;
    int2 s, r, t;
    if (p < npair) {
        s = __ldg((const int2*)edge_src  + p);
        r = __ldg((const int2*)edge_type + p);
        t = __ldg((const int2*)edge_time + p);
    }

    while (p < npair) {
        const int pn = p + ngroup;
        int2 sn, rn, tn;
        if (pn < npair) {                       // prefetch next iteration
            sn = __ldg((const int2*)edge_src  + pn);
            rn = __ldg((const int2*)edge_type + pn);
            tn = __ldg((const int2*)edge_time + pn);
        }

        // Block-strided slots: l (line 0) and l+8 (line 1).
        size_t o0 = (size_t)l;
        size_t o1 = (size_t)l + 8;
        uint4 avA0 = np[(size_t)s.x * 16 + o0], avA1 = np[(size_t)s.x * 16 + o1];
        uint4 bvA0 = rp[(size_t)r.x * 16 + o0], bvA1 = rp[(size_t)r.x * 16 + o1];
        uint4 cvA0 = tp[(size_t)t.x * 16 + o0], cvA1 = tp[(size_t)t.x * 16 + o1];
        uint4 avB0 = np[(size_t)s.y * 16 + o0], avB1 = np[(size_t)s.y * 16 + o1];
        uint4 bvB0 = rp[(size_t)r.y * 16 + o0], bvB1 = rp[(size_t)r.y * 16 + o1];
        uint4 cvB0 = tp[(size_t)t.y * 16 + o0], cvB1 = tp[(size_t)t.y * 16 + o1];

        float dA = edge_partial(avA0, bvA0, cvA0, wv0)
                 + edge_partial(avA1, bvA1, cvA1, wv1);
        float dB = edge_partial(avB0, bvB0, cvB0, wv0)
                 + edge_partial(avB1, bvB1, cvB1, wv1);

#pragma unroll
        for (int off = 4; off; off >>= 1) {
            dA += __shfl_xor_sync(0xffffffffu, dA, off);
            dB += __shfl_xor_sync(0xffffffffu, dB, off);
        }

        if (l == 0) {
            out[p * 2]     = 1.f / (1.f + __expf(-(dA + b2v)));
            out[p * 2 + 1] = 1.f / (1.f + __expf(-(dB + b2v)));
        }

        p = pn; s = sn; r = rn; t = tn;
    }

    // Odd tail edge handled by group 0.
    if ((E & 1) && group == 0) {
        int e = E - 1;
        int se = __ldg(edge_src + e);
        int re = __ldg(edge_type + e);
        int te = __ldg(edge_time + e);
        size_t o0 = (size_t)l;
        size_t o1 = (size_t)l + 8;
        float d = edge_partial(np[(size_t)se * 16 + o0], rp[(size_t)re * 16 + o0],
                               tp[(size_t)te * 16 + o0], wv0)
                + edge_partial(np[(size_t)se * 16 + o1], rp[(size_t)re * 16 + o1],
                               tp[(size_t)te * 16 + o1], wv1);
#pragma unroll
        for (int off = 4; off; off >>= 1)
            d += __shfl_xor_sync(0xffffffffu, d, off);
        if (l == 0)
            out[e] = 1.f / (1.f + __expf(-(d + b2v)));
    }
}

// ---------------------------------------------------------------------------
extern "C" void kernel_launch(void* const* d_in, const int* in_sizes, int n_in,
                              void* d_out, int out_size)
{
    const float* h          = (const float*)d_in[0];
    const int*   edge_index = (const int*)d_in[1];
    const int*   edge_type  = (const int*)d_in[2];
    const int*   edge_time  = (const int*)d_in[3];
    const int*   query_rel  = (const int*)d_in[4];
    const float* rel_table  = (const float*)d_in[5];
    const float* time_table = (const float*)d_in[6];
    const float* W1         = (const float*)d_in[7];
    const float* b1         = (const float*)d_in[8];
    const float* W2         = (const float*)d_in[9];
    const float* b2         = (const float*)d_in[10];
    float*       out        = (float*)d_out;

    const int n_nodes = in_sizes[0] / D;
    const int n_rels  = in_sizes[5] / D;
    const int n_times = in_sizes[6] / D;
    const int E       = in_sizes[2];

    const int nb_node = (n_nodes + BM - 1) / BM;
    const int nb_rel  = (n_rels  + BM - 1) / BM;
    const int nb_time = (n_times + BM - 1) / BM;

    prep_kernel<<<nb_node + nb_rel + nb_time, 256>>>(
        h, rel_table, time_table, W1, b1, W2, query_rel,
        n_nodes, n_rels, n_times);

    edge_kernel<<<2048, 256>>>(edge_index, edge_type, edge_time, b2, out, E);
}